// round 15
// baseline (speedup 1.0000x reference)
#include <cuda_runtime.h>
#include <cuda_fp16.h>

#define NF 6
#define H1 64
#define D 32
#define MAXN 100000
#define MAXE 1600000
#define CSCMAX (MAXE + 8 * MAXN)   // padded CSC

typedef unsigned long long ull;

// ---------------- scratch (static device globals) ----------------------------
__device__ __align__(16) __half g_g1h[(MAXN + 1) * D];   // row MAXN = zero row
__device__ __align__(16) __half g_g2h[(MAXN + 1) * D];
__device__ int    g_cnt[MAXN];        // real in-degree
__device__ int    g_rowptr[MAXN + 1]; // PADDED csc offsets (multiples of 8)
__device__ float  g_dinv[MAXN];
__device__ __align__(16) int g_csc[CSCMAX];
__device__ __align__(16) int g_rank[MAXE];
__device__ int    g_part[128];
__device__ int    g_is64;
__device__ int    g_bar_cnt;
__device__ volatile int g_bar_gen;

// ---------------- helpers ------------------------------------------------------
__device__ __forceinline__ float tanh_fast(float x) {
    float y; asm("tanh.approx.f32 %0, %1;" : "=f"(y) : "f"(x)); return y;
}
__device__ __forceinline__ ull pack2(float lo, float hi) {
    ull r; asm("mov.b64 %0, {%1, %2};" : "=l"(r) : "f"(lo), "f"(hi)); return r;
}
__device__ __forceinline__ void unpack2(ull v, float& lo, float& hi) {
    asm("mov.b64 {%0, %1}, %2;" : "=f"(lo), "=f"(hi) : "l"(v));
}
__device__ __forceinline__ ull fma2(ull a, ull b, ull c) {
    ull d; asm("fma.rn.f32x2 %0, %1, %2, %3;" : "=l"(d) : "l"(a), "l"(b), "l"(c)); return d;
}
__device__ __forceinline__ ull mul2(ull a, ull b) {
    ull d; asm("mul.rn.f32x2 %0, %1, %2;" : "=l"(d) : "l"(a), "l"(b)); return d;
}
__device__ __forceinline__ unsigned cvt_h2(float lo, float hi) {
    unsigned r; asm("cvt.rn.f16x2.f32 %0, %1, %2;" : "=r"(r) : "f"(hi), "f"(lo)); return r;
}
__device__ __forceinline__ unsigned hadd2u(unsigned a, unsigned b) {
    unsigned r; asm("add.f16x2 %0, %1, %2;" : "=r"(r) : "r"(a), "r"(b)); return r;
}
__device__ __forceinline__ uint4 hadd2_4(uint4 a, uint4 b) {
    uint4 r;
    r.x = hadd2u(a.x, b.x);
    r.y = hadd2u(a.y, b.y);
    r.z = hadd2u(a.z, b.z);
    r.w = hadd2u(a.w, b.w);
    return r;
}

__device__ __forceinline__ void grid_sync(int nb) {
    __syncthreads();
    if (threadIdx.x == 0) {
        int gen = g_bar_gen;
        __threadfence();
        if (atomicAdd(&g_bar_cnt, 1) == nb - 1) {
            g_bar_cnt = 0;
            __threadfence();
            g_bar_gen = gen + 1;
        } else {
            while (g_bar_gen == gen) __nanosleep(64);
            __threadfence();
        }
    }
    __syncthreads();
}

__device__ __forceinline__ int e_src(const void* e, int i, int E, bool is64) {
    return is64 ? ((const int*)e)[2 * i] : ((const int*)e)[i];
}
__device__ __forceinline__ int e_dst(const void* e, int i, int E, bool is64) {
    return is64 ? ((const int*)e)[2 * (E + i)] : ((const int*)e)[E + i];
}
__device__ __forceinline__ int4 ldcs4(const int4* p) {
    int4 v;
    asm("ld.global.cs.v4.s32 {%0,%1,%2,%3}, [%4];"
        : "=r"(v.x), "=r"(v.y), "=r"(v.z), "=r"(v.w) : "l"(p));
    return v;
}
__device__ __forceinline__ int4 dst4(const void* e, int i, int E, bool is64) {
    if (is64) {
        int4 w0 = ldcs4(((const int4*)e) + ((E + 4 * i) >> 1));
        int4 w1 = ldcs4(((const int4*)e) + ((E + 4 * i) >> 1) + 1);
        return make_int4(w0.x, w0.z, w1.x, w1.z);
    }
    return ldcs4(((const int4*)e) + ((E + 4 * i) >> 2));
}
__device__ __forceinline__ int4 src4(const void* e, int i, bool is64) {
    if (is64) {
        int4 w0 = ldcs4(((const int4*)e) + 2 * i);
        int4 w1 = ldcs4(((const int4*)e) + 2 * i + 1);
        return make_int4(w0.x, w0.z, w1.x, w1.z);
    }
    return ldcs4(((const int4*)e) + i);
}

#define HSTRIDE 40   // sH row stride in halfs: 80B, 16B-aligned rows, LDS.128-friendly

// 32x32 matvec: hrow pulled into registers with 4 LDS.128 (conflict-free),
// then pure FFMA2 with W via uniform LDS.128 broadcasts.
__device__ __forceinline__ void matvec32(const float* sW, const __half* hrow, ull* acc) {
    uint4 hv[2];
    hv[0] = ((const uint4*)hrow)[0];
    hv[1] = ((const uint4*)hrow)[1];
    uint4 hv2[2];
    hv2[0] = ((const uint4*)hrow)[2];
    hv2[1] = ((const uint4*)hrow)[3];
    unsigned hw_[16];
    hw_[0] = hv[0].x;  hw_[1] = hv[0].y;  hw_[2] = hv[0].z;  hw_[3] = hv[0].w;
    hw_[4] = hv[1].x;  hw_[5] = hv[1].y;  hw_[6] = hv[1].z;  hw_[7] = hv[1].w;
    hw_[8] = hv2[0].x; hw_[9] = hv2[0].y; hw_[10] = hv2[0].z; hw_[11] = hv2[0].w;
    hw_[12] = hv2[1].x; hw_[13] = hv2[1].y; hw_[14] = hv2[1].z; hw_[15] = hv2[1].w;
#pragma unroll 4
    for (int kk = 0; kk < 16; kk++) {
        float2 hp = __half22float2(*(__half2*)&hw_[kk]);
#pragma unroll
        for (int half_ = 0; half_ < 2; half_++) {
            int k = 2 * kk + half_;
            float hk = half_ ? hp.y : hp.x;
            ull hk2 = pack2(hk, hk);
            const ulonglong2* w = (const ulonglong2*)(sW + k * 32);
#pragma unroll
            for (int m = 0; m < 8; m++) {
                ulonglong2 q = w[m];
                acc[2 * m]     = fma2(hk2, q.x, acc[2 * m]);
                acc[2 * m + 1] = fma2(hk2, q.y, acc[2 * m + 1]);
            }
        }
    }
}

__device__ __forceinline__ void store_h16(__half* dst, ull* acc, float di) {
    ull di2 = pack2(di, di);
    unsigned r[16];
#pragma unroll
    for (int m = 0; m < 16; m++) {
        float lo, hi;
        unpack2(mul2(acc[m], di2), lo, hi);
        r[m] = cvt_h2(lo, hi);
    }
    uint4* p = (uint4*)dst;
    p[0] = make_uint4(r[0], r[1], r[2], r[3]);
    p[1] = make_uint4(r[4], r[5], r[6], r[7]);
    p[2] = make_uint4(r[8], r[9], r[10], r[11]);
    p[3] = make_uint4(r[12], r[13], r[14], r[15]);
}

// add a uint4 (8 fp16 channels) into 8 fp32 accumulators
__device__ __forceinline__ void add8(uint4 q, float* a) {
    float2 f;
    f = __half22float2(*(__half2*)&q.x); a[0] += f.x; a[1] += f.y;
    f = __half22float2(*(__half2*)&q.y); a[2] += f.x; a[3] += f.y;
    f = __half22float2(*(__half2*)&q.z); a[4] += f.x; a[5] += f.y;
    f = __half22float2(*(__half2*)&q.w); a[6] += f.x; a[7] += f.y;
}

// octet gather: 4 lanes per node, 8 fp16 channels per lane (uint4 = 16B).
// Lists padded to multiples of 8 -> single exact loop. Edge pairs pre-combined
// with HADD2. csc read with streaming hint (single use).
__device__ __forceinline__ void gather_node8(
    const uint4* __restrict__ feat, const int* __restrict__ rp,
    int node, int ol, float4 bA, float4 bB, float di, unsigned* outr)
{
    int beg = rp[node], end = rp[node + 1];
    float a[8], b[8];
    {
        uint4 sf = feat[node * 4 + ol];
        float2 f;
        f = __half22float2(*(__half2*)&sf.x); a[0] = f.x; a[1] = f.y;
        f = __half22float2(*(__half2*)&sf.y); a[2] = f.x; a[3] = f.y;
        f = __half22float2(*(__half2*)&sf.z); a[4] = f.x; a[5] = f.y;
        f = __half22float2(*(__half2*)&sf.w); a[6] = f.x; a[7] = f.y;
    }
#pragma unroll
    for (int j = 0; j < 8; j++) b[j] = 0.f;
    for (int e = beg; e < end; e += 8) {
        int4 s0 = ldcs4((const int4*)(g_csc + e));
        int4 s1 = ldcs4((const int4*)(g_csc + e + 4));
        uint4 q0 = feat[s0.x * 4 + ol];
        uint4 q1 = feat[s0.y * 4 + ol];
        uint4 q2 = feat[s0.z * 4 + ol];
        uint4 q3 = feat[s0.w * 4 + ol];
        uint4 q4 = feat[s1.x * 4 + ol];
        uint4 q5 = feat[s1.y * 4 + ol];
        uint4 q6 = feat[s1.z * 4 + ol];
        uint4 q7 = feat[s1.w * 4 + ol];
        uint4 p0 = hadd2_4(q0, q1);
        uint4 p1 = hadd2_4(q2, q3);
        uint4 p2 = hadd2_4(q4, q5);
        uint4 p3 = hadd2_4(q6, q7);
        add8(p0, a); add8(p1, b); add8(p2, a); add8(p3, b);
    }
    float h[8];
#pragma unroll
    for (int j = 0; j < 4; j++)
        h[j] = fmaxf(fmaf(a[j] + b[j], di, (&bA.x)[j]), 0.f);
#pragma unroll
    for (int j = 0; j < 4; j++)
        h[4 + j] = fmaxf(fmaf(a[4 + j] + b[4 + j], di, (&bB.x)[j]), 0.f);
    outr[0] = cvt_h2(h[0], h[1]);
    outr[1] = cvt_h2(h[2], h[3]);
    outr[2] = cvt_h2(h[4], h[5]);
    outr[3] = cvt_h2(h[6], h[7]);
}

// ---------------- the single persistent kernel --------------------------------
__global__ void __launch_bounds__(256, 3) k_mega(
    const float* __restrict__ x, const void* __restrict__ ei,
    const float* __restrict__ We1, const float* __restrict__ be1,
    const float* __restrict__ We2, const float* __restrict__ be2,
    const float* __restrict__ Wg1, const float* __restrict__ bg1,
    const float* __restrict__ Wg2, const float* __restrict__ bg2,
    const float* __restrict__ Wp1, const float* __restrict__ bp1,
    const float* __restrict__ Wp2, const float* __restrict__ bp2,
    float* __restrict__ out, int N, int E, int nb)
{
    __shared__ __align__(16) __half sH[256 * HSTRIDE];   // 20480 B
    __shared__ __align__(16) float  sW[3680];            // 14720 B
    __shared__ int swsum[8];

    const int tid  = threadIdx.x;
    const int lane = tid & 31;
    const int wid  = tid >> 5;
    const int gtid = blockIdx.x * 256 + tid;
    const int gstride = nb * 256;
    const int gwarp = blockIdx.x * 8 + wid;
    const int wstride = nb * 8;
    const bool vec = ((E & 3) == 0);
    const int ow = lane >> 2;     // node-in-group (0..7)
    const int ol = lane & 3;      // channel-octet within node (0..3)

    // ---- phase 0: zero counters + zero rows + dtype detect ----
    for (int i = gtid; i < N; i += gstride) g_cnt[i] = 0;
    for (int i = gtid; i < 2 * D; i += gstride) {
        if (i < D) g_g1h[N * D + i] = __float2half(0.f);
        else       g_g2h[N * D + (i - D)] = __float2half(0.f);
    }
    if (blockIdx.x == 0 && wid == 0) {
        int v = 0;
        for (int j = lane; j < 2048; j += 32) v |= ((const int*)ei)[2 * j + 1];
#pragma unroll
        for (int off = 16; off; off >>= 1) v |= __shfl_xor_sync(0xffffffffu, v, off);
        if (lane == 0) g_is64 = (v == 0) ? 1 : 0;
    }
    grid_sync(nb);

    const bool is64 = (__ldcg(&g_is64) != 0);

    // ---- phase 1: in-degree histogram + rank ----
    if (vec) {
        int nE4 = E >> 2;
        for (int i = gtid; i < nE4; i += gstride) {
            int4 d = dst4(ei, i, E, is64);
            int4 r;
            r.x = atomicAdd(&g_cnt[d.x], 1);
            r.y = atomicAdd(&g_cnt[d.y], 1);
            r.z = atomicAdd(&g_cnt[d.z], 1);
            r.w = atomicAdd(&g_cnt[d.w], 1);
            ((int4*)g_rank)[i] = r;
        }
    } else {
        for (int i = gtid; i < E; i += gstride)
            g_rank[i] = atomicAdd(&g_cnt[e_dst(ei, i, E, is64)], 1);
    }
    grid_sync(nb);

    // ---- phase 2a: per-chunk (1024) exclusive scan of PADDED degrees ----
    const int nchunk = (N + 1023) >> 10;
    for (int c = blockIdx.x; c < nchunk; c += nb) {
        int i0 = (c << 10) + tid * 4;
        int v0 = (i0 + 0 < N) ? ((__ldcg(&g_cnt[i0 + 0]) + 7) & ~7) : 0;
        int v1 = (i0 + 1 < N) ? ((__ldcg(&g_cnt[i0 + 1]) + 7) & ~7) : 0;
        int v2 = (i0 + 2 < N) ? ((__ldcg(&g_cnt[i0 + 2]) + 7) & ~7) : 0;
        int v3 = (i0 + 3 < N) ? ((__ldcg(&g_cnt[i0 + 3]) + 7) & ~7) : 0;
        int ts = v0 + v1 + v2 + v3;
        int s = ts;
#pragma unroll
        for (int off = 1; off < 32; off <<= 1) {
            int t = __shfl_up_sync(0xffffffffu, s, off);
            if (lane >= off) s += t;
        }
        if (lane == 31) swsum[wid] = s;
        __syncthreads();
        if (wid == 0 && lane < 8) {
            int w = swsum[lane];
            int ws = w;
#pragma unroll
            for (int off = 1; off < 8; off <<= 1) {
                int t = __shfl_up_sync(0xffu, ws, off, 8);
                if (lane >= off) ws += t;
            }
            swsum[lane] = ws - w;
        }
        __syncthreads();
        int excl = s - ts + swsum[wid];
        if (i0 + 0 < N) g_rowptr[i0 + 0] = excl; excl += v0;
        if (i0 + 1 < N) g_rowptr[i0 + 1] = excl; excl += v1;
        if (i0 + 2 < N) g_rowptr[i0 + 2] = excl; excl += v2;
        if (i0 + 3 < N) g_rowptr[i0 + 3] = excl; excl += v3;
        if (tid == 255) g_part[c] = excl;
        __syncthreads();
    }
    grid_sync(nb);

    // ---- phase 2b: scan chunk totals ----
    if (blockIdx.x == 0 && wid == 0) {
        int b4 = lane * 4;
        int p0 = (b4 + 0 < nchunk) ? __ldcg(&g_part[b4 + 0]) : 0;
        int p1 = (b4 + 1 < nchunk) ? __ldcg(&g_part[b4 + 1]) : 0;
        int p2 = (b4 + 2 < nchunk) ? __ldcg(&g_part[b4 + 2]) : 0;
        int p3 = (b4 + 3 < nchunk) ? __ldcg(&g_part[b4 + 3]) : 0;
        int ts = p0 + p1 + p2 + p3;
        int s = ts;
#pragma unroll
        for (int off = 1; off < 32; off <<= 1) {
            int t = __shfl_up_sync(0xffffffffu, s, off);
            if (lane >= off) s += t;
        }
        int excl = s - ts;
        if (b4 + 0 < nchunk) g_part[b4 + 0] = excl; excl += p0;
        if (b4 + 1 < nchunk) g_part[b4 + 1] = excl; excl += p1;
        if (b4 + 2 < nchunk) g_part[b4 + 2] = excl; excl += p2;
        if (b4 + 3 < nchunk) g_part[b4 + 3] = excl; excl += p3;
    }
    grid_sync(nb);

    // ---- phase 2c: global rowptr + dinv ----
    for (int i = gtid; i < N; i += gstride) {
        int deg = __ldcg(&g_cnt[i]);
        int r = __ldcg(&g_rowptr[i]) + __ldcg(&g_part[i >> 10]);
        g_rowptr[i] = r;
        g_dinv[i] = rsqrtf((float)(deg + 1));
        if (i == N - 1) g_rowptr[N] = r + ((deg + 7) & ~7);
    }
    grid_sync(nb);

    // ---- phase 3: stage embed weights + CSC fill (+ padding) + embed MLP ----
    for (int i = tid; i < NF * H1; i += 256) {
        int f = i >> 6, k = i & 63;
        sW[k * 8 + f] = We1[i];
    }
    for (int i = tid; i < H1;     i += 256) sW[512 + i] = be1[i];
    for (int i = tid; i < H1 * D; i += 256) sW[576 + i] = We2[i];
    for (int i = tid; i < D;      i += 256) sW[2624 + i] = be2[i];
    for (int i = tid; i < D * D;  i += 256) sW[2656 + i] = Wg1[i];

    // pad each node's list with the zero node (index N)
    for (int i = gtid; i < N; i += gstride) {
        int beg = g_rowptr[i] + g_cnt[i];
        int end = g_rowptr[i + 1];
        for (int e = beg; e < end; e++) g_csc[e] = N;
    }
    if (vec) {
        int nE4 = E >> 2;
        for (int i = gtid; i < nE4; i += gstride) {
            int4 s = src4(ei, i, is64);
            int4 d = dst4(ei, i, E, is64);
            int4 r = ((const int4*)g_rank)[i];
            g_csc[g_rowptr[d.x] + r.x] = s.x;
            g_csc[g_rowptr[d.y] + r.y] = s.y;
            g_csc[g_rowptr[d.z] + r.z] = s.z;
            g_csc[g_rowptr[d.w] + r.w] = s.w;
        }
    } else {
        for (int i = gtid; i < E; i += gstride) {
            int s = e_src(ei, i, E, is64);
            int d = e_dst(ei, i, E, is64);
            g_csc[g_rowptr[d] + g_rank[i]] = s;
        }
    }
    __syncthreads();

    {
        const float* sWe1T = sW;
        const float* sbe1  = sW + 512;
        const float* sWe2  = sW + 576;
        const float* sbe2  = sW + 2624;
        const float* sWg1  = sW + 2656;
        __half* hrow = sH + tid * HSTRIDE;
        unsigned* hrow32 = (unsigned*)hrow;

        for (int node = gtid; node < N; node += gstride) {
            const float2* xp = (const float2*)(x + node * NF);
            float2 x01 = xp[0], x23 = xp[1], x45 = xp[2];
            ull xp01 = pack2(x01.x, x01.y);
            ull xp23 = pack2(x23.x, x23.y);
            ull xp45 = pack2(x45.x, x45.y);

            ull acc[16];
#pragma unroll
            for (int m = 0; m < 16; m++) acc[m] = ((const ull*)sbe2)[m];

#pragma unroll 2
            for (int k = 0; k < H1; k++) {
                const ulonglong2* w1 = (const ulonglong2*)(sWe1T + k * 8);
                ulonglong2 qa = w1[0];
                ulonglong2 qb = w1[1];
                ull tp = fma2(xp01, qa.x, fma2(xp23, qa.y, fma2(xp45, qb.x, pack2(sbe1[k], 0.f))));
                float lo, hi; unpack2(tp, lo, hi);
                float hk = tanh_fast(lo + hi);
                ull hk2 = pack2(hk, hk);
                const ulonglong2* w2 = (const ulonglong2*)(sWe2 + k * 32);
#pragma unroll
                for (int m = 0; m < 8; m++) {
                    ulonglong2 q = w2[m];
                    acc[2 * m]     = fma2(hk2, q.x, acc[2 * m]);
                    acc[2 * m + 1] = fma2(hk2, q.y, acc[2 * m + 1]);
                }
            }
#pragma unroll
            for (int m = 0; m < 16; m++) {
                float lo, hi; unpack2(acc[m], lo, hi);
                hrow32[m] = cvt_h2(tanh_fast(lo), tanh_fast(hi));
            }
            ull acc2[16];
#pragma unroll
            for (int m = 0; m < 16; m++) acc2[m] = 0ull;
            matvec32(sWg1, hrow, acc2);
            store_h16(g_g1h + node * D, acc2, g_dinv[node]);
        }
    }
    grid_sync(nb);

    // ---- phase 4: gather conv1 (8 nodes/warp, padded lists) + relu -> @Wg2 * dinv ----
    {
        for (int i = tid; i < D * D; i += 256) sW[i] = Wg2[i];
        for (int i = tid; i < D;     i += 256) sW[1024 + i] = bg1[i];
        __syncthreads();
        const int nch = (N + 31) >> 5;
        const uint4* feat = (const uint4*)g_g1h;
        float4 bA = ((const float4*)(sW + 1024))[2 * ol];
        float4 bB = ((const float4*)(sW + 1024))[2 * ol + 1];

        for (int c = gwarp; c < nch; c += wstride) {
            int base = c << 5;
#pragma unroll 1
            for (int i = 0; i < 4; i++) {
                int node = base + 8 * i + ow;
                if (node < N) {
                    unsigned r[4];
                    gather_node8(feat, g_rowptr, node, ol, bA, bB, g_dinv[node], r);
                    unsigned* row = (unsigned*)(sH + (wid * 32 + 8 * i + ow) * HSTRIDE);
                    row[ol * 4 + 0] = r[0];
                    row[ol * 4 + 1] = r[1];
                    row[ol * 4 + 2] = r[2];
                    row[ol * 4 + 3] = r[3];
                }
            }
            __syncwarp();
            int node = base + lane;
            if (node < N) {
                ull acc[16];
#pragma unroll
                for (int m = 0; m < 16; m++) acc[m] = 0ull;
                matvec32(sW, sH + (wid * 32 + lane) * HSTRIDE, acc);
                store_h16(g_g2h + node * D, acc, g_dinv[node]);
            }
            __syncwarp();
        }
    }
    grid_sync(nb);

    // ---- phase 5: gather conv2 (8 nodes/warp, padded lists) + relu -> @Wp1 -> tanh -> @Wp2 -> tanh ----
    {
        for (int i = tid; i < D * D; i += 256) sW[i] = Wp1[i];
        for (int i = tid; i < D;     i += 256) {
            sW[1024 + i] = bg2[i];
            sW[1056 + i] = bp1[i];
            sW[1088 + i] = Wp2[i];
        }
        if (tid == 0) sW[1120] = bp2[0];
        __syncthreads();
        const int nch = (N + 31) >> 5;
        const uint4* feat = (const uint4*)g_g2h;
        float4 bA = ((const float4*)(sW + 1024))[2 * ol];
        float4 bB = ((const float4*)(sW + 1024))[2 * ol + 1];

        for (int c = gwarp; c < nch; c += wstride) {
            int base = c << 5;
#pragma unroll 1
            for (int i = 0; i < 4; i++) {
                int node = base + 8 * i + ow;
                if (node < N) {
                    unsigned r[4];
                    gather_node8(feat, g_rowptr, node, ol, bA, bB, g_dinv[node], r);
                    unsigned* row = (unsigned*)(sH + (wid * 32 + 8 * i + ow) * HSTRIDE);
                    row[ol * 4 + 0] = r[0];
                    row[ol * 4 + 1] = r[1];
                    row[ol * 4 + 2] = r[2];
                    row[ol * 4 + 3] = r[3];
                }
            }
            __syncwarp();
            int node = base + lane;
            if (node < N) {
                ull acc[16];
#pragma unroll
                for (int m = 0; m < 16; m++) acc[m] = ((const ull*)(sW + 1056))[m];
                matvec32(sW, sH + (wid * 32 + lane) * HSTRIDE, acc);
                float s = 0.f;
#pragma unroll
                for (int m = 0; m < 16; m++) {
                    float lo, hi; unpack2(acc[m], lo, hi);
                    s = fmaf(tanh_fast(lo), sW[1088 + 2 * m], s);
                    s = fmaf(tanh_fast(hi), sW[1088 + 2 * m + 1], s);
                }
                out[node] = tanhf(s + sW[1120]);
            }
            __syncwarp();
        }
    }
}

// ---------------- launch -------------------------------------------------------
extern "C" void kernel_launch(void* const* d_in, const int* in_sizes, int n_in,
                              void* d_out, int out_size)
{
    const float* x   = (const float*)d_in[0];
    const void*  ei  = d_in[1];
    const float* We1 = (const float*)d_in[2];
    const float* be1 = (const float*)d_in[3];
    const float* We2 = (const float*)d_in[4];
    const float* be2 = (const float*)d_in[5];
    const float* Wg1 = (const float*)d_in[6];
    const float* bg1 = (const float*)d_in[7];
    const float* Wg2 = (const float*)d_in[8];
    const float* bg2 = (const float*)d_in[9];
    const float* Wp1 = (const float*)d_in[10];
    const float* bp1 = (const float*)d_in[11];
    const float* Wp2 = (const float*)d_in[12];
    const float* bp2 = (const float*)d_in[13];

    int N = in_sizes[0] / NF;
    int E = in_sizes[1] / 2;
    if (N > MAXN) N = MAXN;
    if (E > MAXE) E = MAXE;

    int dev = 0, sms = 0, bpm = 0;
    cudaGetDevice(&dev);
    cudaDeviceGetAttribute(&sms, cudaDevAttrMultiProcessorCount, dev);
    cudaOccupancyMaxActiveBlocksPerMultiprocessor(&bpm, k_mega, 256, 0);
    if (bpm < 1) bpm = 1;
    int nb = sms * bpm;
    if (nb > 4096) nb = 4096;

    k_mega<<<nb, 256>>>(x, ei, We1, be1, We2, be2, Wg1, bg1, Wg2, bg2,
                        Wp1, bp1, Wp2, bp2, (float*)d_out, N, E, nb);
}

// round 16
// speedup vs baseline: 1.0497x; 1.0497x over previous
#include <cuda_runtime.h>
#include <cuda_fp16.h>

#define NF 6
#define H1 64
#define D 32
#define MAXN 100000
#define MAXE 1600000
#define CSCMAX (MAXE + 8 * MAXN)   // padded CSC

typedef unsigned long long ull;

// ---------------- scratch (static device globals) ----------------------------
__device__ __align__(16) __half g_g1h[(MAXN + 1) * D];   // row MAXN = zero row
__device__ __align__(16) __half g_g2h[(MAXN + 1) * D];
__device__ int    g_cnt[MAXN];        // real in-degree (live through gather phases)
__device__ int    g_rowptr[MAXN];     // PADDED csc start offsets (atomic-allocated)
__device__ float  g_dinv[MAXN];
__device__ __align__(16) int g_csc[CSCMAX];
__device__ __align__(16) int g_rank[MAXE];
__device__ int    g_total;            // allocation cursor
__device__ int    g_is64;
__device__ int    g_bar_cnt;
__device__ volatile int g_bar_gen;

// ---------------- helpers ------------------------------------------------------
__device__ __forceinline__ float tanh_fast(float x) {
    float y; asm("tanh.approx.f32 %0, %1;" : "=f"(y) : "f"(x)); return y;
}
__device__ __forceinline__ ull pack2(float lo, float hi) {
    ull r; asm("mov.b64 %0, {%1, %2};" : "=l"(r) : "f"(lo), "f"(hi)); return r;
}
__device__ __forceinline__ void unpack2(ull v, float& lo, float& hi) {
    asm("mov.b64 {%0, %1}, %2;" : "=f"(lo), "=f"(hi) : "l"(v));
}
__device__ __forceinline__ ull fma2(ull a, ull b, ull c) {
    ull d; asm("fma.rn.f32x2 %0, %1, %2, %3;" : "=l"(d) : "l"(a), "l"(b), "l"(c)); return d;
}
__device__ __forceinline__ ull mul2(ull a, ull b) {
    ull d; asm("mul.rn.f32x2 %0, %1, %2;" : "=l"(d) : "l"(a), "l"(b)); return d;
}
__device__ __forceinline__ unsigned cvt_h2(float lo, float hi) {
    unsigned r; asm("cvt.rn.f16x2.f32 %0, %1, %2;" : "=r"(r) : "f"(hi), "f"(lo)); return r;
}
__device__ __forceinline__ unsigned hadd2u(unsigned a, unsigned b) {
    unsigned r; asm("add.f16x2 %0, %1, %2;" : "=r"(r) : "r"(a), "r"(b)); return r;
}
__device__ __forceinline__ uint4 hadd2_4(uint4 a, uint4 b) {
    uint4 r;
    r.x = hadd2u(a.x, b.x);
    r.y = hadd2u(a.y, b.y);
    r.z = hadd2u(a.z, b.z);
    r.w = hadd2u(a.w, b.w);
    return r;
}

__device__ __forceinline__ void grid_sync(int nb) {
    __syncthreads();
    if (threadIdx.x == 0) {
        int gen = g_bar_gen;
        __threadfence();
        if (atomicAdd(&g_bar_cnt, 1) == nb - 1) {
            g_bar_cnt = 0;
            __threadfence();
            g_bar_gen = gen + 1;
        } else {
            while (g_bar_gen == gen) __nanosleep(64);
            __threadfence();
        }
    }
    __syncthreads();
}

__device__ __forceinline__ int e_src(const void* e, int i, int E, bool is64) {
    return is64 ? ((const int*)e)[2 * i] : ((const int*)e)[i];
}
__device__ __forceinline__ int e_dst(const void* e, int i, int E, bool is64) {
    return is64 ? ((const int*)e)[2 * (E + i)] : ((const int*)e)[E + i];
}
__device__ __forceinline__ int4 dst4(const void* e, int i, int E, bool is64) {
    if (is64) {
        int4 w0 = ((const int4*)e)[((E + 4 * i) >> 1)];
        int4 w1 = ((const int4*)e)[((E + 4 * i) >> 1) + 1];
        return make_int4(w0.x, w0.z, w1.x, w1.z);
    }
    return ((const int4*)e)[(E + 4 * i) >> 2];
}
__device__ __forceinline__ int4 src4(const void* e, int i, bool is64) {
    if (is64) {
        int4 w0 = ((const int4*)e)[2 * i];
        int4 w1 = ((const int4*)e)[2 * i + 1];
        return make_int4(w0.x, w0.z, w1.x, w1.z);
    }
    return ((const int4*)e)[i];
}

// 32x32 matvec: per-thread acc (16 packed f32x2), W uniform LDS.128 broadcast.
__device__ __forceinline__ void matvec32(const float* sW, const __half* hrow, ull* acc) {
#pragma unroll 4
    for (int k = 0; k < 32; k++) {
        float hk = __half2float(hrow[k]);
        ull hk2 = pack2(hk, hk);
        const ulonglong2* w = (const ulonglong2*)(sW + k * 32);
#pragma unroll
        for (int m = 0; m < 8; m++) {
            ulonglong2 q = w[m];
            acc[2 * m]     = fma2(hk2, q.x, acc[2 * m]);
            acc[2 * m + 1] = fma2(hk2, q.y, acc[2 * m + 1]);
        }
    }
}

__device__ __forceinline__ void store_h16(__half* dst, ull* acc, float di) {
    ull di2 = pack2(di, di);
    unsigned r[16];
#pragma unroll
    for (int m = 0; m < 16; m++) {
        float lo, hi;
        unpack2(mul2(acc[m], di2), lo, hi);
        r[m] = cvt_h2(lo, hi);
    }
    uint4* p = (uint4*)dst;
    p[0] = make_uint4(r[0], r[1], r[2], r[3]);
    p[1] = make_uint4(r[4], r[5], r[6], r[7]);
    p[2] = make_uint4(r[8], r[9], r[10], r[11]);
    p[3] = make_uint4(r[12], r[13], r[14], r[15]);
}

#define HSTRIDE 34   // sH row stride in halfs (gcd(17,32)=1 -> conflict-free)

// add a uint4 (8 fp16 channels) into 8 fp32 accumulators
__device__ __forceinline__ void add8(uint4 q, float* a) {
    float2 f;
    f = __half22float2(*(__half2*)&q.x); a[0] += f.x; a[1] += f.y;
    f = __half22float2(*(__half2*)&q.y); a[2] += f.x; a[3] += f.y;
    f = __half22float2(*(__half2*)&q.z); a[4] += f.x; a[5] += f.y;
    f = __half22float2(*(__half2*)&q.w); a[6] += f.x; a[7] += f.y;
}

// octet gather: 4 lanes per node, 8 fp16 channels per lane (uint4 = 16B).
// Lists padded to multiples of 8 -> single exact loop. Edge pairs pre-combined
// with HADD2 (fp16) before fp32 accumulation. [beg, end) from rowptr + padded cnt.
__device__ __forceinline__ void gather_node8(
    const uint4* __restrict__ feat,
    int beg, int end,
    int node, int ol, float4 bA, float4 bB, float di, unsigned* outr)
{
    float a[8], b[8];
    {
        uint4 sf = feat[node * 4 + ol];
        float2 f;
        f = __half22float2(*(__half2*)&sf.x); a[0] = f.x; a[1] = f.y;
        f = __half22float2(*(__half2*)&sf.y); a[2] = f.x; a[3] = f.y;
        f = __half22float2(*(__half2*)&sf.z); a[4] = f.x; a[5] = f.y;
        f = __half22float2(*(__half2*)&sf.w); a[6] = f.x; a[7] = f.y;
    }
#pragma unroll
    for (int j = 0; j < 8; j++) b[j] = 0.f;
    for (int e = beg; e < end; e += 8) {
        int4 s0 = *(const int4*)(g_csc + e);
        int4 s1 = *(const int4*)(g_csc + e + 4);
        uint4 q0 = feat[s0.x * 4 + ol];
        uint4 q1 = feat[s0.y * 4 + ol];
        uint4 q2 = feat[s0.z * 4 + ol];
        uint4 q3 = feat[s0.w * 4 + ol];
        uint4 q4 = feat[s1.x * 4 + ol];
        uint4 q5 = feat[s1.y * 4 + ol];
        uint4 q6 = feat[s1.z * 4 + ol];
        uint4 q7 = feat[s1.w * 4 + ol];
        uint4 p0 = hadd2_4(q0, q1);
        uint4 p1 = hadd2_4(q2, q3);
        uint4 p2 = hadd2_4(q4, q5);
        uint4 p3 = hadd2_4(q6, q7);
        add8(p0, a); add8(p1, b); add8(p2, a); add8(p3, b);
    }
    float h[8];
#pragma unroll
    for (int j = 0; j < 4; j++)
        h[j] = fmaxf(fmaf(a[j] + b[j], di, (&bA.x)[j]), 0.f);
#pragma unroll
    for (int j = 0; j < 4; j++)
        h[4 + j] = fmaxf(fmaf(a[4 + j] + b[4 + j], di, (&bB.x)[j]), 0.f);
    outr[0] = cvt_h2(h[0], h[1]);
    outr[1] = cvt_h2(h[2], h[3]);
    outr[2] = cvt_h2(h[4], h[5]);
    outr[3] = cvt_h2(h[6], h[7]);
}

// ---------------- the single persistent kernel --------------------------------
__global__ void __launch_bounds__(256, 3) k_mega(
    const float* __restrict__ x, const void* __restrict__ ei,
    const float* __restrict__ We1, const float* __restrict__ be1,
    const float* __restrict__ We2, const float* __restrict__ be2,
    const float* __restrict__ Wg1, const float* __restrict__ bg1,
    const float* __restrict__ Wg2, const float* __restrict__ bg2,
    const float* __restrict__ Wp1, const float* __restrict__ bp1,
    const float* __restrict__ Wp2, const float* __restrict__ bp2,
    float* __restrict__ out, int N, int E, int nb)
{
    __shared__ __align__(16) __half sH[256 * HSTRIDE];
    __shared__ __align__(16) float  sW[3680];

    const int tid  = threadIdx.x;
    const int lane = tid & 31;
    const int wid  = tid >> 5;
    const int gtid = blockIdx.x * 256 + tid;
    const int gstride = nb * 256;
    const int gwarp = blockIdx.x * 8 + wid;
    const int wstride = nb * 8;
    const bool vec = ((E & 3) == 0);
    const int ow = lane >> 2;     // node-in-group (0..7)
    const int ol = lane & 3;      // channel-octet within node (0..3)

    // ---- phase 0: zero counters + zero rows + cursor + dtype detect ----
    for (int i = gtid; i < N; i += gstride) g_cnt[i] = 0;
    for (int i = gtid; i < 2 * D; i += gstride) {
        if (i < D) g_g1h[N * D + i] = __float2half(0.f);
        else       g_g2h[N * D + (i - D)] = __float2half(0.f);
    }
    if (gtid == 0) g_total = 0;
    if (blockIdx.x == 0 && wid == 0) {
        int v = 0;
        for (int j = lane; j < 2048; j += 32) v |= ((const int*)ei)[2 * j + 1];
#pragma unroll
        for (int off = 16; off; off >>= 1) v |= __shfl_xor_sync(0xffffffffu, v, off);
        if (lane == 0) g_is64 = (v == 0) ? 1 : 0;
    }
    grid_sync(nb);

    const bool is64 = (__ldcg(&g_is64) != 0);

    // ---- phase 1: in-degree histogram + rank ----
    if (vec) {
        int nE4 = E >> 2;
        for (int i = gtid; i < nE4; i += gstride) {
            int4 d = dst4(ei, i, E, is64);
            int4 r;
            r.x = atomicAdd(&g_cnt[d.x], 1);
            r.y = atomicAdd(&g_cnt[d.y], 1);
            r.z = atomicAdd(&g_cnt[d.z], 1);
            r.w = atomicAdd(&g_cnt[d.w], 1);
            ((int4*)g_rank)[i] = r;
        }
    } else {
        for (int i = gtid; i < E; i += gstride)
            g_rank[i] = atomicAdd(&g_cnt[e_dst(ei, i, E, is64)], 1);
    }
    grid_sync(nb);

    // ---- phase 2: atomic bump allocation of padded buckets + dinv ----
    for (int i = gtid; i < N; i += gstride) {
        int deg = __ldcg(&g_cnt[i]);
        int pad = (deg + 7) & ~7;
        g_rowptr[i] = atomicAdd(&g_total, pad);
        g_dinv[i] = rsqrtf((float)(deg + 1));
    }
    grid_sync(nb);

    // ---- phase 3: stage embed weights + CSC fill (+ padding) + embed MLP ----
    for (int i = tid; i < NF * H1; i += 256) {
        int f = i >> 6, k = i & 63;
        sW[k * 8 + f] = We1[i];
    }
    for (int i = tid; i < H1;     i += 256) sW[512 + i] = be1[i];
    for (int i = tid; i < H1 * D; i += 256) sW[576 + i] = We2[i];
    for (int i = tid; i < D;      i += 256) sW[2624 + i] = be2[i];
    for (int i = tid; i < D * D;  i += 256) sW[2656 + i] = Wg1[i];

    // pad each node's list tail with the zero node (index N)
    for (int i = gtid; i < N; i += gstride) {
        int cnt = g_cnt[i];
        int beg = g_rowptr[i] + cnt;
        int end = g_rowptr[i] + ((cnt + 7) & ~7);
        for (int e = beg; e < end; e++) g_csc[e] = N;
    }
    if (vec) {
        int nE4 = E >> 2;
        for (int i = gtid; i < nE4; i += gstride) {
            int4 s = src4(ei, i, is64);
            int4 d = dst4(ei, i, E, is64);
            int4 r = ((const int4*)g_rank)[i];
            g_csc[g_rowptr[d.x] + r.x] = s.x;
            g_csc[g_rowptr[d.y] + r.y] = s.y;
            g_csc[g_rowptr[d.z] + r.z] = s.z;
            g_csc[g_rowptr[d.w] + r.w] = s.w;
        }
    } else {
        for (int i = gtid; i < E; i += gstride) {
            int s = e_src(ei, i, E, is64);
            int d = e_dst(ei, i, E, is64);
            g_csc[g_rowptr[d] + g_rank[i]] = s;
        }
    }
    __syncthreads();

    {
        const float* sWe1T = sW;
        const float* sbe1  = sW + 512;
        const float* sWe2  = sW + 576;
        const float* sbe2  = sW + 2624;
        const float* sWg1  = sW + 2656;
        __half* hrow = sH + tid * HSTRIDE;
        unsigned* hrow32 = (unsigned*)hrow;

        for (int node = gtid; node < N; node += gstride) {
            const float2* xp = (const float2*)(x + node * NF);
            float2 x01 = xp[0], x23 = xp[1], x45 = xp[2];
            ull xp01 = pack2(x01.x, x01.y);
            ull xp23 = pack2(x23.x, x23.y);
            ull xp45 = pack2(x45.x, x45.y);

            ull acc[16];
#pragma unroll
            for (int m = 0; m < 16; m++) acc[m] = ((const ull*)sbe2)[m];

#pragma unroll 2
            for (int k = 0; k < H1; k++) {
                const ulonglong2* w1 = (const ulonglong2*)(sWe1T + k * 8);
                ulonglong2 qa = w1[0];
                ulonglong2 qb = w1[1];
                ull tp = fma2(xp01, qa.x, fma2(xp23, qa.y, fma2(xp45, qb.x, pack2(sbe1[k], 0.f))));
                float lo, hi; unpack2(tp, lo, hi);
                float hk = tanh_fast(lo + hi);
                ull hk2 = pack2(hk, hk);
                const ulonglong2* w2 = (const ulonglong2*)(sWe2 + k * 32);
#pragma unroll
                for (int m = 0; m < 8; m++) {
                    ulonglong2 q = w2[m];
                    acc[2 * m]     = fma2(hk2, q.x, acc[2 * m]);
                    acc[2 * m + 1] = fma2(hk2, q.y, acc[2 * m + 1]);
                }
            }
#pragma unroll
            for (int m = 0; m < 16; m++) {
                float lo, hi; unpack2(acc[m], lo, hi);
                hrow32[m] = cvt_h2(tanh_fast(lo), tanh_fast(hi));
            }
            ull acc2[16];
#pragma unroll
            for (int m = 0; m < 16; m++) acc2[m] = 0ull;
            matvec32(sWg1, hrow, acc2);
            store_h16(g_g1h + node * D, acc2, g_dinv[node]);
        }
    }
    grid_sync(nb);

    // ---- phase 4: gather conv1 (8 nodes/warp, padded lists) + relu -> @Wg2 * dinv ----
    {
        for (int i = tid; i < D * D; i += 256) sW[i] = Wg2[i];
        for (int i = tid; i < D;     i += 256) sW[1024 + i] = bg1[i];
        __syncthreads();
        const int nch = (N + 31) >> 5;
        const uint4* feat = (const uint4*)g_g1h;
        float4 bA = ((const float4*)(sW + 1024))[2 * ol];
        float4 bB = ((const float4*)(sW + 1024))[2 * ol + 1];

        for (int c = gwarp; c < nch; c += wstride) {
            int base = c << 5;
#pragma unroll 1
            for (int i = 0; i < 4; i++) {
                int node = base + 8 * i + ow;
                if (node < N) {
                    int beg = g_rowptr[node];
                    int end = beg + ((g_cnt[node] + 7) & ~7);
                    unsigned r[4];
                    gather_node8(feat, beg, end, node, ol, bA, bB, g_dinv[node], r);
                    unsigned* row = (unsigned*)(sH + (wid * 32 + 8 * i + ow) * HSTRIDE);
                    row[ol * 4 + 0] = r[0];
                    row[ol * 4 + 1] = r[1];
                    row[ol * 4 + 2] = r[2];
                    row[ol * 4 + 3] = r[3];
                }
            }
            __syncwarp();
            int node = base + lane;
            if (node < N) {
                ull acc[16];
#pragma unroll
                for (int m = 0; m < 16; m++) acc[m] = 0ull;
                matvec32(sW, sH + (wid * 32 + lane) * HSTRIDE, acc);
                store_h16(g_g2h + node * D, acc, g_dinv[node]);
            }
            __syncwarp();
        }
    }
    grid_sync(nb);

    // ---- phase 5: gather conv2 (8 nodes/warp, padded lists) + relu -> @Wp1 -> tanh -> @Wp2 -> tanh ----
    {
        for (int i = tid; i < D * D; i += 256) sW[i] = Wp1[i];
        for (int i = tid; i < D;     i += 256) {
            sW[1024 + i] = bg2[i];
            sW[1056 + i] = bp1[i];
            sW[1088 + i] = Wp2[i];
        }
        if (tid == 0) sW[1120] = bp2[0];
        __syncthreads();
        const int nch = (N + 31) >> 5;
        const uint4* feat = (const uint4*)g_g2h;
        float4 bA = ((const float4*)(sW + 1024))[2 * ol];
        float4 bB = ((const float4*)(sW + 1024))[2 * ol + 1];

        for (int c = gwarp; c < nch; c += wstride) {
            int base = c << 5;
#pragma unroll 1
            for (int i = 0; i < 4; i++) {
                int node = base + 8 * i + ow;
                if (node < N) {
                    int beg = g_rowptr[node];
                    int end = beg + ((g_cnt[node] + 7) & ~7);
                    unsigned r[4];
                    gather_node8(feat, beg, end, node, ol, bA, bB, g_dinv[node], r);
                    unsigned* row = (unsigned*)(sH + (wid * 32 + 8 * i + ow) * HSTRIDE);
                    row[ol * 4 + 0] = r[0];
                    row[ol * 4 + 1] = r[1];
                    row[ol * 4 + 2] = r[2];
                    row[ol * 4 + 3] = r[3];
                }
            }
            __syncwarp();
            int node = base + lane;
            if (node < N) {
                ull acc[16];
#pragma unroll
                for (int m = 0; m < 16; m++) acc[m] = ((const ull*)(sW + 1056))[m];
                matvec32(sW, sH + (wid * 32 + lane) * HSTRIDE, acc);
                float s = 0.f;
#pragma unroll
                for (int m = 0; m < 16; m++) {
                    float lo, hi; unpack2(acc[m], lo, hi);
                    s = fmaf(tanh_fast(lo), sW[1088 + 2 * m], s);
                    s = fmaf(tanh_fast(hi), sW[1088 + 2 * m + 1], s);
                }
                out[node] = tanhf(s + sW[1120]);
            }
            __syncwarp();
        }
    }
}

// ---------------- launch -------------------------------------------------------
extern "C" void kernel_launch(void* const* d_in, const int* in_sizes, int n_in,
                              void* d_out, int out_size)
{
    const float* x   = (const float*)d_in[0];
    const void*  ei  = d_in[1];
    const float* We1 = (const float*)d_in[2];
    const float* be1 = (const float*)d_in[3];
    const float* We2 = (const float*)d_in[4];
    const float* be2 = (const float*)d_in[5];
    const float* Wg1 = (const float*)d_in[6];
    const float* bg1 = (const float*)d_in[7];
    const float* Wg2 = (const float*)d_in[8];
    const float* bg2 = (const float*)d_in[9];
    const float* Wp1 = (const float*)d_in[10];
    const float* bp1 = (const float*)d_in[11];
    const float* Wp2 = (const float*)d_in[12];
    const float* bp2 = (const float*)d_in[13];

    int N = in_sizes[0] / NF;
    int E = in_sizes[1] / 2;
    if (N > MAXN) N = MAXN;
    if (E > MAXE) E = MAXE;

    int dev = 0, sms = 0, bpm = 0;
    cudaGetDevice(&dev);
    cudaDeviceGetAttribute(&sms, cudaDevAttrMultiProcessorCount, dev);
    cudaOccupancyMaxActiveBlocksPerMultiprocessor(&bpm, k_mega, 256, 0);
    if (bpm < 1) bpm = 1;
    int nb = sms * bpm;
    if (nb > 4096) nb = 4096;

    k_mega<<<nb, 256>>>(x, ei, We1, be1, We2, be2, Wg1, bg1, Wg2, bg2,
                        Wp1, bp1, Wp2, bp2, (float*)d_out, N, E, nb);
}